// round 17
// baseline (speedup 1.0000x reference)
#include <cuda_runtime.h>
#include <math.h>

#define BATCH 64
#define DMODEL 4096
#define NHEADS 32
#define KVHEADS 8
#define HDIM 128
#define NMAT 48
#define KSPLIT 8
#define KCHUNK (DMODEL / KSPLIT)   // 512
#define CACHE_HALF 67108864L       // 65536 * 8 * 128
#define ATTN_OUT_OFF 134217728L    // 2 * CACHE_HALF
#define ASPLIT 4
#define NCOPY_QKV 1024
#define NCOPY_ATTN 640
#define NCOPY_O 384

// ---------------- scratch (allocation-free, __device__ globals) ----------------
__device__ __align__(16) float g_qkv_part[NMAT * KSPLIT * BATCH * HDIM];
__device__ __align__(16) float g_qbuf[BATCH * NHEADS * HDIM];
__device__ __align__(16) float g_kbuf[BATCH * KVHEADS * HDIM];
__device__ __align__(16) float g_vbuf[BATCH * KVHEADS * HDIM];
__device__ __align__(16) float g_obuf[BATCH * NHEADS * HDIM];
__device__ __align__(16) float g_opart[4 * BATCH * DMODEL];
__device__ __align__(16) float g_apart[BATCH * KVHEADS * ASPLIT * 520];

// ---------------- packed f32x2 helpers (FFMA2 — PTX-only on sm_103a) ----------------
__device__ __forceinline__ unsigned long long pack2(float lo, float hi) {
    unsigned long long r;
    asm("mov.b64 %0, {%1, %2};" : "=l"(r) : "f"(lo), "f"(hi));
    return r;
}
__device__ __forceinline__ void fma2(unsigned long long& acc, unsigned long long a, unsigned long long b) {
    asm("fma.rn.f32x2 %0, %1, %2, %0;" : "+l"(acc) : "l"(a), "l"(b));
}
__device__ __forceinline__ unsigned long long mul2(unsigned long long a, unsigned long long b) {
    unsigned long long r;
    asm("mul.rn.f32x2 %0, %1, %2;" : "=l"(r) : "l"(a), "l"(b));
    return r;
}
__device__ __forceinline__ float2 unpack2(unsigned long long v) {
    float2 f;
    asm("mov.b64 {%0, %1}, %2;" : "=f"(f.x), "=f"(f.y) : "l"(v));
    return f;
}

// ---------------- cp.async helpers ----------------
__device__ __forceinline__ void cp_async16(void* dst, const void* src) {
    unsigned d = (unsigned)__cvta_generic_to_shared(dst);
    asm volatile("cp.async.cg.shared.global [%0], [%1], 16;\n" :: "r"(d), "l"(src));
}
#define CP_COMMIT() asm volatile("cp.async.commit_group;" ::: "memory")
#define CP_WAIT(n)  asm volatile("cp.async.wait_group %0;" :: "n"(n) : "memory")

// ---------------- shared copy path ----------------
__device__ __forceinline__ void copy_rows(int cid,
                                          const float* __restrict__ cache,
                                          const int* __restrict__ slot_mapping,
                                          float* __restrict__ out,
                                          int* s_slots, int* s_skip)
{
    int t = threadIdx.x;
    if (t < 64) s_slots[t] = slot_mapping[t];
    __syncthreads();
    long r0 = (long)cid << 6;
    if (t < 64) {
        int slot = (int)((r0 + t) & 65535L);
        int sk = 0;
#pragma unroll 8
        for (int i = 0; i < 64; i++) sk |= (s_slots[i] == slot);
        s_skip[t] = sk;
    }
    __syncthreads();
    const float4* src = (const float4*)cache + (r0 << 8) + t;
    float4*       dst = (float4*)out         + (r0 << 8) + t;
#pragma unroll 8
    for (int it = 0; it < 64; it++) {
        if (!s_skip[it]) dst[it * 256] = src[it * 256];
    }
}

// ---------------- Kernel 1: QKV projection (FFMA2) + copy blocks, interleaved ----------------
__global__ __launch_bounds__(256) void qkv_copy_kernel(
    const float* __restrict__ x,
    const float* __restrict__ q_w,
    const float* __restrict__ kv_w,
    const float* __restrict__ cache,
    const int*   __restrict__ slot_mapping,
    float*       __restrict__ out)
{
    __shared__ __align__(16) float xs[64][36];
    __shared__ __align__(16) float ws[32][132];
    __shared__ int s_slots[64];
    __shared__ int s_skip[64];

    int bid = blockIdx.x;
    // interleave: groups of 11 = 6 gemm + 5 copy (64 groups: 384 gemm, 320... keep old split)
    if (bid >= NMAT * KSPLIT) {
        copy_rows(bid - NMAT * KSPLIT, cache, slot_mapping, out, s_slots, s_skip);
        return;
    }
    int mat = bid >> 3;
    int ks  = bid & 7;
    const float* W = (mat < 32) ? (q_w  + (size_t)mat * DMODEL * HDIM)
                                : (kv_w + (size_t)(mat - 32) * DMODEL * HDIM);
    int d0 = ks * KCHUNK;

    int t  = threadIdx.x;
    int ty = t >> 4;
    int tx = t & 15;

    unsigned long long acc[4][4];
#pragma unroll
    for (int i = 0; i < 4; i++)
#pragma unroll
        for (int j = 0; j < 4; j++) acc[i][j] = 0ULL;

    for (int dt = 0; dt < KCHUNK; dt += 32) {
#pragma unroll
        for (int r = 0; r < 2; r++) {
            int f = t + 256 * r;
            int row = f >> 3, q4 = f & 7;
            *(float4*)&xs[row][q4 * 4] =
                *(const float4*)(x + (size_t)row * DMODEL + d0 + dt + q4 * 4);
        }
#pragma unroll
        for (int r = 0; r < 4; r++) {
            int f = t + 256 * r;
            int row = f >> 5, q4 = f & 31;
            *(float4*)&ws[row][q4 * 4] =
                *(const float4*)(W + (size_t)(d0 + dt + row) * HDIM + q4 * 4);
        }
        __syncthreads();
#pragma unroll
        for (int kk = 0; kk < 32; kk++) {
            unsigned long long ap0 = pack2(xs[ty * 4 + 0][kk], xs[ty * 4 + 0][kk]);
            unsigned long long ap1 = pack2(xs[ty * 4 + 1][kk], xs[ty * 4 + 1][kk]);
            unsigned long long ap2 = pack2(xs[ty * 4 + 2][kk], xs[ty * 4 + 2][kk]);
            unsigned long long ap3 = pack2(xs[ty * 4 + 3][kk], xs[ty * 4 + 3][kk]);
            ulonglong2 b01 = *(const ulonglong2*)&ws[kk][tx * 8];
            ulonglong2 b23 = *(const ulonglong2*)&ws[kk][tx * 8 + 4];
            fma2(acc[0][0], ap0, b01.x); fma2(acc[0][1], ap0, b01.y);
            fma2(acc[0][2], ap0, b23.x); fma2(acc[0][3], ap0, b23.y);
            fma2(acc[1][0], ap1, b01.x); fma2(acc[1][1], ap1, b01.y);
            fma2(acc[1][2], ap1, b23.x); fma2(acc[1][3], ap1, b23.y);
            fma2(acc[2][0], ap2, b01.x); fma2(acc[2][1], ap2, b01.y);
            fma2(acc[2][2], ap2, b23.x); fma2(acc[2][3], ap2, b23.y);
            fma2(acc[3][0], ap3, b01.x); fma2(acc[3][1], ap3, b01.y);
            fma2(acc[3][2], ap3, b23.x); fma2(acc[3][3], ap3, b23.y);
        }
        __syncthreads();
    }

    float* dst = g_qkv_part + ((size_t)(mat * 8 + ks) * 64) * 128;
#pragma unroll
    for (int i = 0; i < 4; i++) {
        int row = ty * 4 + i;
        float2 u0 = unpack2(acc[i][0]), u1 = unpack2(acc[i][1]);
        float2 u2 = unpack2(acc[i][2]), u3 = unpack2(acc[i][3]);
        *(float4*)&dst[row * 128 + tx * 8]     = make_float4(u0.x, u0.y, u1.x, u1.y);
        *(float4*)&dst[row * 128 + tx * 8 + 4] = make_float4(u2.x, u2.y, u3.x, u3.y);
    }
}

// ---------------- Kernel 2: reduce K-split partials + RoPE ----------------
__global__ __launch_bounds__(256) void reduce_rope(const int* __restrict__ context_lens)
{
    int tid = blockIdx.x * 256 + threadIdx.x;
    if (tid >= NMAT * BATCH * 64) return;
    int mat = tid >> 12;
    int rem = tid & 4095;
    int b = rem >> 6;
    int j = rem & 63;

    float v1 = 0.f, v2 = 0.f;
    size_t off = ((size_t)(mat * 8) * 64 + b) * 128;
#pragma unroll
    for (int ks = 0; ks < 8; ks++) {
        v1 += g_qkv_part[off + j];
        v2 += g_qkv_part[off + 64 + j];
        off += 64 * 128;
    }

    float o1 = v1, o2 = v2;
    if (mat < 40) {
        float pos = (float)(context_lens[b] - 1);
        float ts = powf(10000.0f, (float)j * (1.0f / 64.0f));
        float ang = pos / ts;
        float s = sinf(ang), c = cosf(ang);
        o1 = v1 * c - v2 * s;
        o2 = v2 * c + v1 * s;
    }

    if (mat < 32) {
        float* d = g_qbuf + ((size_t)b * 32 + mat) * 128;
        d[j] = o1; d[j + 64] = o2;
    } else if (mat < 40) {
        float* d = g_kbuf + ((size_t)b * 8 + (mat - 32)) * 128;
        d[j] = o1; d[j + 64] = o2;
    } else {
        float* d = g_vbuf + ((size_t)b * 8 + (mat - 40)) * 128;
        d[j] = o1; d[j + 64] = o2;
    }
}

// ---------------- Kernel 3: scatter new k/v rows ----------------
__global__ void cache_scatter(const int* __restrict__ slot_mapping, float* __restrict__ out)
{
    int b = blockIdx.x;
    int slot = slot_mapping[b];
    int t = threadIdx.x;
    const float4* ksrc = (const float4*)(g_kbuf + (size_t)b * 1024);
    const float4* vsrc = (const float4*)(g_vbuf + (size_t)b * 1024);
    float4* dk = (float4*)(out + (size_t)slot * 1024);
    float4* dv = (float4*)(out + CACHE_HALF + (size_t)slot * 1024);
    dk[t] = ksrc[t];
    dv[t] = vsrc[t];
}

// ---------------- Kernel 4: split-KV attention (double-buffered) + copy blocks ----------------
struct AttnSmem {
    float k[2][32][132];
    float v[2][32][132];
    float q[4][132];
    float logit[4][32];
    float prob[4][32];
    float m[4], newm[4], corr[4];
    int   bt[16];
    int   slots[64];
    int   skip[64];
};

__global__ __launch_bounds__(256) void attn_copy_kernel(
    const float* __restrict__ cache,
    const int*   __restrict__ block_tables,
    const int*   __restrict__ context_lens,
    const int*   __restrict__ slot_mapping,
    float*       __restrict__ out)
{
    extern __shared__ __align__(16) char smem_raw[];
    AttnSmem& S = *reinterpret_cast<AttnSmem*>(smem_raw);

    int bid = blockIdx.x;
    int grp = bid / 21, lane = bid % 21;     // 16 attn + 5 copy per group
    if (lane >= 16) {
        copy_rows(NCOPY_QKV + grp * 5 + (lane - 16), cache, slot_mapping, out, S.slots, S.skip);
        return;
    }
    int aid = grp * 16 + lane;
    int b   = aid >> 5;
    int kvh = (aid >> 2) & 7;
    int sp  = aid & 3;
    int t = threadIdx.x;

    int ctx = context_lens[b];
    int start = sp << 8;
    long pbase = (long)aid * 520;
    if (start >= ctx) {
        if (t < 4) {
            g_apart[pbase + 512 + t] = -INFINITY;
            g_apart[pbase + 516 + t] = 0.f;
        }
        return;
    }
    int end = min(ctx, start + 256);

    if (t < 16) S.bt[t] = block_tables[b * 64 + sp * 16 + t];

    const float sm_scale = 0.08838834764831845f;
#pragma unroll
    for (int r = 0; r < 2; r++) {
        int f = t + 256 * r;
        int g = f >> 7, h = f & 127;
        S.q[g][h] = g_qbuf[((size_t)b * 32 + kvh * 4 + g) * 128 + h] * sm_scale;
    }
    if (t < 4) S.m[t] = -INFINITY;

    unsigned long long accp = 0ULL;
    float lsum = 0.f;
    int g2 = t >> 6;
    int hh = t & 63;
    __syncthreads();

    const float* kc = cache;
    const float* vc = cache + CACHE_HALF;

    int nchunk = (end - start + 31) >> 5;

    auto load_chunk = [&](int c, int buf) {
        int p0 = start + (c << 5);
#pragma unroll
        for (int r = 0; r < 4; r++) {
            int f = t + 256 * r;
            int row = f >> 5;
            int q4  = f & 31;
            int pos = p0 + row;
            int posc = min(pos, ctx - 1);
            const float* ks;
            const float* vs;
            if (posc == ctx - 1) {
                ks = g_kbuf + ((size_t)b * 8 + kvh) * 128 + q4 * 4;
                vs = g_vbuf + ((size_t)b * 8 + kvh) * 128 + q4 * 4;
            } else {
                int slot = S.bt[(posc >> 4) & 15] * 16 + (posc & 15);
                size_t off = (size_t)slot * 1024 + kvh * 128 + q4 * 4;
                ks = kc + off;
                vs = vc + off;
            }
            cp_async16(&S.k[buf][row][q4 * 4], ks);
            cp_async16(&S.v[buf][row][q4 * 4], vs);
        }
        CP_COMMIT();
    };

    load_chunk(0, 0);

    for (int c = 0; c < nchunk; c++) {
        int cur = c & 1;
        int p0 = start + (c << 5);
        if (c + 1 < nchunk) {
            load_chunk(c + 1, cur ^ 1);
            CP_WAIT(1);
        } else {
            CP_WAIT(0);
        }
        __syncthreads();

        // phase 1: logits (f32x2 dot)
        if (t < 128) {
            int g = t & 3, i = t >> 2;
            int pos = p0 + i;
            float lg = -1e30f;
            if (pos < ctx) {
                unsigned long long s0 = 0ULL, s1 = 0ULL;
#pragma unroll
                for (int j = 0; j < 32; j++) {
                    ulonglong2 qv = *(const ulonglong2*)&S.q[g][j * 4];
                    ulonglong2 kv = *(const ulonglong2*)&S.k[cur][i][j * 4];
                    fma2(s0, qv.x, kv.x);
                    fma2(s1, qv.y, kv.y);
                }
                float2 r0 = unpack2(s0), r1 = unpack2(s1);
                lg = (r0.x + r0.y) + (r1.x + r1.y);
            }
            S.logit[g][i] = lg;
        }
        __syncthreads();

        // phase 2a: chunk max + probs
        if (t < 128) {
            int g = t & 3, i = t >> 2;
            float cmax = -INFINITY;
#pragma unroll
            for (int ii = 0; ii < 32; ii++) cmax = fmaxf(cmax, S.logit[g][ii]);
            float newm = fmaxf(S.m[g], cmax);
            float lg = S.logit[g][i];
            S.prob[g][i] = (lg > -1e29f) ? expf(lg - newm) : 0.f;
            if (i == 0) { S.newm[g] = newm; S.corr[g] = expf(S.m[g] - newm); }
        }
        __syncthreads();

        // phase 2b: rescale + accumulate AV (f32x2)
        {
            float corr = S.corr[g2];
            accp = mul2(accp, pack2(corr, corr));
            lsum *= corr;
            float psum = 0.f;
#pragma unroll
            for (int i = 0; i < 32; i++) {
                float p = S.prob[g2][i];
                psum += p;
                unsigned long long vv = *(const unsigned long long*)&S.v[cur][i][hh * 2];
                fma2(accp, pack2(p, p), vv);
            }
            lsum += psum;
            if (hh == 0) S.m[g2] = S.newm[g2];
        }
        __syncthreads();
    }

    float2 av = unpack2(accp);
    *(float2*)&g_apart[pbase + g2 * 128 + hh * 2] = av;
    if (hh == 0) {
        g_apart[pbase + 512 + g2] = S.m[g2];
        g_apart[pbase + 516 + g2] = lsum;
    }
}

// ---------------- Kernel 5: combine attention splits ----------------
__global__ __launch_bounds__(256) void attn_combine()
{
    int b   = blockIdx.x >> 3;
    int kvh = blockIdx.x & 7;
    int t = threadIdx.x;
    int g  = t >> 6;
    int hh = t & 63;

    long base0 = ((long)(b * 8 + kvh) * 4) * 520;
    float m0 = g_apart[base0 + 0 * 520 + 512 + g];
    float m1 = g_apart[base0 + 1 * 520 + 512 + g];
    float m2 = g_apart[base0 + 2 * 520 + 512 + g];
    float m3 = g_apart[base0 + 3 * 520 + 512 + g];
    float M = fmaxf(fmaxf(m0, m1), fmaxf(m2, m3));

    float num0 = 0.f, num1 = 0.f, den = 0.f;
#pragma unroll
    for (int sp = 0; sp < 4; sp++) {
        long bs = base0 + sp * 520;
        float w = expf(g_apart[bs + 512 + g] - M);
        den  += w * g_apart[bs + 516 + g];
        num0 += w * g_apart[bs + g * 128 + hh * 2];
        num1 += w * g_apart[bs + g * 128 + hh * 2 + 1];
    }
    float inv = 1.0f / den;
    int n = kvh * 4 + g;
    *(float2*)&g_obuf[((size_t)b * 32 + n) * 128 + hh * 2] = make_float2(num0 * inv, num1 * inv);
}

// ---------------- Kernel 6: O projection (FFMA2) + copy blocks ----------------
__global__ __launch_bounds__(256) void o_copy_kernel(
    const float* __restrict__ o_w,
    const float* __restrict__ cache,
    const int*   __restrict__ slot_mapping,
    float*       __restrict__ out)
{
    __shared__ __align__(16) float as_[64][36];
    __shared__ __align__(16) float ws[32][68];
    __shared__ int s_slots[64];
    __shared__ int s_skip[64];

    int bid = blockIdx.x;
    int grp = bid / 5, lane = bid % 5;
    if (lane >= 2) {
        copy_rows(NCOPY_QKV + NCOPY_ATTN + grp * 3 + (lane - 2), cache, slot_mapping, out, s_slots, s_skip);
        return;
    }
    int oid = grp * 2 + lane;
    int nt = oid >> 2;
    int ks = oid & 3;
    int d0 = nt * 64;
    int k0 = ks * 1024;

    int t = threadIdx.x;
    int ty = t >> 4, tx = t & 15;
    unsigned long long acc[4][2];
#pragma unroll
    for (int i = 0; i < 4; i++) { acc[i][0] = 0ULL; acc[i][1] = 0ULL; }

    for (int kt = 0; kt < 1024; kt += 32) {
#pragma unroll
        for (int r = 0; r < 2; r++) {
            int f = t + 256 * r;
            int row = f >> 3, q4 = f & 7;
            *(float4*)&as_[row][q4 * 4] =
                *(const float4*)(g_obuf + (size_t)row * DMODEL + k0 + kt + q4 * 4);
        }
#pragma unroll
        for (int r = 0; r < 2; r++) {
            int f = t + 256 * r;
            int row = f >> 4, q4 = f & 15;
            *(float4*)&ws[row][q4 * 4] =
                *(const float4*)(o_w + (size_t)(k0 + kt + row) * DMODEL + d0 + q4 * 4);
        }
        __syncthreads();
#pragma unroll
        for (int kk = 0; kk < 32; kk++) {
            unsigned long long ap0 = pack2(as_[ty * 4 + 0][kk], as_[ty * 4 + 0][kk]);
            unsigned long long ap1 = pack2(as_[ty * 4 + 1][kk], as_[ty * 4 + 1][kk]);
            unsigned long long ap2 = pack2(as_[ty * 4 + 2][kk], as_[ty * 4 + 2][kk]);
            unsigned long long ap3 = pack2(as_[ty * 4 + 3][kk], as_[ty * 4 + 3][kk]);
            ulonglong2 bp = *(const ulonglong2*)&ws[kk][tx * 4];
            fma2(acc[0][0], ap0, bp.x); fma2(acc[0][1], ap0, bp.y);
            fma2(acc[1][0], ap1, bp.x); fma2(acc[1][1], ap1, bp.y);
            fma2(acc[2][0], ap2, bp.x); fma2(acc[2][1], ap2, bp.y);
            fma2(acc[3][0], ap3, bp.x); fma2(acc[3][1], ap3, bp.y);
        }
        __syncthreads();
    }

    float* dst = g_opart + (size_t)ks * BATCH * DMODEL;
#pragma unroll
    for (int i = 0; i < 4; i++) {
        float2 p0 = unpack2(acc[i][0]), p1 = unpack2(acc[i][1]);
        *(float4*)&dst[(size_t)(ty * 4 + i) * DMODEL + d0 + tx * 4] =
            make_float4(p0.x, p0.y, p1.x, p1.y);
    }
}

// ---------------- Kernel 7: reduce the 4 K-split partials into d_out ----------------
__global__ void o_reduce(float* __restrict__ out_attn)
{
    int i = blockIdx.x * 256 + threadIdx.x;
    float s = g_opart[i]
            + g_opart[i + BATCH * DMODEL]
            + g_opart[i + 2 * BATCH * DMODEL]
            + g_opart[i + 3 * BATCH * DMODEL];
    out_attn[i] = s;
}

// ---------------- launch ----------------
extern "C" void kernel_launch(void* const* d_in, const int* in_sizes, int n_in,
                              void* d_out, int out_size)
{
    const float* x            = (const float*)d_in[0];
    const int*   slot_mapping = (const int*)d_in[2];
    const int*   block_tables = (const int*)d_in[3];
    const int*   context_lens = (const int*)d_in[4];
    const float* cache        = (const float*)d_in[5];
    const float* q_w          = (const float*)d_in[6];
    const float* kv_w         = (const float*)d_in[7];
    const float* o_w          = (const float*)d_in[8];
    float* out = (float*)d_out;

    // 1) QKV projection + copy blocks
    qkv_copy_kernel<<<NMAT * KSPLIT + NCOPY_QKV, 256>>>(x, q_w, kv_w, cache, slot_mapping, out);

    // 2) K-split reduce + RoPE
    reduce_rope<<<(NMAT * BATCH * 64 + 255) / 256, 256>>>(context_lens);

    // 3) write the new k/v rows
    cache_scatter<<<BATCH, 256>>>(slot_mapping, out);

    // 4) split-KV attention (double-buffered, dynamic smem) + copy blocks
    int attn_smem = (int)sizeof(AttnSmem);
    cudaFuncSetAttribute(attn_copy_kernel, cudaFuncAttributeMaxDynamicSharedMemorySize, attn_smem);
    attn_copy_kernel<<<(2048 / 16) * 21, 256, attn_smem>>>(cache, block_tables, context_lens, slot_mapping, out);

    // 5) combine split partials
    attn_combine<<<BATCH * KVHEADS, 256>>>();

    // 6) O projection + copy blocks
    o_copy_kernel<<<(256 / 2) * 5, 256>>>(o_w, cache, slot_mapping, out);

    // 7) final K-split reduce
    o_reduce<<<(BATCH * DMODEL) / 256, 256>>>(out + ATTN_OUT_OFF);
}